// round 7
// baseline (speedup 1.0000x reference)
#include <cuda_runtime.h>
#include <cstdint>

#define B_ 4
#define S_ 1024
#define E_ 1024
#define H_ 16
#define D_ 64

__device__ float g_qkv[3*B_*S_*E_];
__device__ float g_ctx[B_*S_*E_];
__device__ float g_xtf[B_*S_*E_];
__device__ float g_wtf[4*E_*E_];
__device__ float g_g[B_*E_];
__device__ float g_gq[B_*E_];
__device__ float g_gk[B_*E_];
__device__ float g_minv[B_];

__device__ __forceinline__ uint32_t fbits(float f) { return __float_as_uint(f); }

__device__ __forceinline__ uint32_t f2tf(float f) {
    uint32_t u;
    asm("cvt.rna.tf32.f32 %0, %1;" : "=r"(u) : "f"(f));
    return u;
}
__device__ __forceinline__ float tfround(float f) {
    return __uint_as_float(f2tf(f));
}

__device__ __forceinline__ void mma_tf32(float c[4],
    uint32_t a0, uint32_t a1, uint32_t a2, uint32_t a3,
    uint32_t b0, uint32_t b1)
{
    asm volatile(
        "mma.sync.aligned.m16n8k8.row.col.f32.tf32.tf32.f32 "
        "{%0,%1,%2,%3}, {%4,%5,%6,%7}, {%8,%9}, {%0,%1,%2,%3};"
        : "+f"(c[0]), "+f"(c[1]), "+f"(c[2]), "+f"(c[3])
        : "r"(a0), "r"(a1), "r"(a2), "r"(a3), "r"(b0), "r"(b1));
}

__device__ __forceinline__ void cp16(uint32_t saddr, const void* g) {
    asm volatile("cp.async.cg.shared.global [%0], [%1], 16;" :: "r"(saddr), "l"(g));
}

// ---------------------------------------------------------------------------
__global__ void __launch_bounds__(256) round_all(
    const float4* __restrict__ x,
    const float4* __restrict__ wq, const float4* __restrict__ wk,
    const float4* __restrict__ wv, const float4* __restrict__ wo)
{
    int idx = blockIdx.x * 256 + threadIdx.x;
    const float4* src;
    float4* dst;
    if (idx < (1 << 20)) {
        src = x + idx;
        dst = (float4*)g_xtf + idx;
    } else {
        int r = idx - (1 << 20);
        int w = r >> 18, o = r & ((1 << 18) - 1);
        const float4* s = (w == 0) ? wq : (w == 1) ? wk : (w == 2) ? wv : wo;
        src = s + o;
        dst = (float4*)g_wtf + ((size_t)w << 18) + o;
    }
    float4 v = *src;
    v.x = tfround(v.x); v.y = tfround(v.y);
    v.z = tfround(v.z); v.w = tfround(v.w);
    *dst = v;
}

// ---------------------------------------------------------------------------
__global__ void msum_kernel(const int* __restrict__ mask) {
    int b = threadIdx.x >> 5, lane = threadIdx.x & 31;
    float s = 0.f;
    for (int j = lane; j < S_; j += 32) s += (float)mask[b*S_ + j];
    #pragma unroll
    for (int o = 16; o; o >>= 1) s += __shfl_xor_sync(0xffffffffu, s, o);
    if (lane == 0) g_minv[b] = 1.0f / fmaxf(s, 1e-9f);
}

__global__ void mean_kernel(const float* __restrict__ x, const int* __restrict__ mask) {
    __shared__ float part[4][64];
    int b  = blockIdx.y;
    int e0 = blockIdx.x * 64;
    int el = threadIdx.x & 63, sq = threadIdx.x >> 6;
    float acc = 0.f;
    int sbeg = sq * 256;
    for (int s = sbeg; s < sbeg + 256; s++) {
        float m = (float)mask[b*S_ + s];
        acc += x[((size_t)s*B_ + b)*E_ + e0 + el] * m;
    }
    part[sq][el] = acc;
    __syncthreads();
    if (threadIdx.x < 64) {
        float t = part[0][el] + part[1][el] + part[2][el] + part[3][el];
        g_g[b*E_ + e0 + el] = t * g_minv[b];
    }
}

// ---------------------------------------------------------------------------
// tf32 GEMM core; inputs already tf32-rounded -> raw-bit fragment loads.
#define GPAD 20
#define GSTG (128*GPAD)

__device__ __forceinline__ void tgemm_body(
    const float* __restrict__ A, const float* __restrict__ W,
    const float* __restrict__ bias, float* __restrict__ Y,
    int permIn, int permOut, int roundOut, int bx, int by,
    float (*As)[GSTG], float (*Bs)[GSTG])
{
    const int tid = threadIdx.x;
    const int lane = tid & 31, warp = tid >> 5;
    const int wm = (warp & 1) * 64, wn = (warp >> 1) * 32;
    const int r4 = lane >> 2, c4 = lane & 3;

    uint32_t aBase = (uint32_t)__cvta_generic_to_shared(&As[0][0]);
    uint32_t bBase = (uint32_t)__cvta_generic_to_shared(&Bs[0][0]);

    int row0 = tid >> 2,         k40 = (tid & 3) * 4;
    int row1 = (tid + 256) >> 2, k41 = ((tid + 256) & 3) * 4;
    int am0 = by*128 + row0;
    int am1 = by*128 + row1;
    int ar0 = permIn ? ((am0 & 1023)*B_ + (am0 >> 10)) : am0;
    int ar1 = permIn ? ((am1 & 1023)*B_ + (am1 >> 10)) : am1;
    const float* ap0 = A + (size_t)ar0*1024 + k40;
    const float* ap1 = A + (size_t)ar1*1024 + k41;
    const float* wp0 = W + ((size_t)(bx*128 + row0))*1024 + k40;
    const float* wp1 = W + ((size_t)(bx*128 + row1))*1024 + k41;
    uint32_t ad0 = aBase + (row0*GPAD + k40)*4, ad1 = aBase + (row1*GPAD + k41)*4;
    uint32_t bd0 = bBase + (row0*GPAD + k40)*4, bd1 = bBase + (row1*GPAD + k41)*4;

    auto loadStage = [&](int stg, int k0) {
        uint32_t so = stg * GSTG * 4;
        cp16(ad0 + so, ap0 + k0);
        cp16(ad1 + so, ap1 + k0);
        cp16(bd0 + so, wp0 + k0);
        cp16(bd1 + so, wp1 + k0);
        asm volatile("cp.async.commit_group;" ::: "memory");
    };

    float acc[4][4][4];
    #pragma unroll
    for (int mi = 0; mi < 4; mi++)
        #pragma unroll
        for (int nj = 0; nj < 4; nj++)
            #pragma unroll
            for (int t = 0; t < 4; t++) acc[mi][nj][t] = 0.f;

    loadStage(0, 0);
    for (int ks = 0; ks < 64; ks++) {
        if (ks < 63) {
            loadStage((ks + 1) & 1, (ks + 1) * 16);
            asm volatile("cp.async.wait_group 1;" ::: "memory");
        } else {
            asm volatile("cp.async.wait_group 0;" ::: "memory");
        }
        __syncthreads();
        const float* as = As[ks & 1];
        const float* bs = Bs[ks & 1];
        #pragma unroll
        for (int kk = 0; kk < 16; kk += 8) {
            uint32_t af[4][4];
            #pragma unroll
            for (int mi = 0; mi < 4; mi++) {
                const float* ap = as + (wm + mi*16 + r4)*GPAD + kk + c4;
                af[mi][0] = fbits(ap[0]);
                af[mi][1] = fbits(ap[8*GPAD]);
                af[mi][2] = fbits(ap[4]);
                af[mi][3] = fbits(ap[8*GPAD + 4]);
            }
            #pragma unroll
            for (int nj = 0; nj < 4; nj++) {
                const float* bp = bs + (wn + nj*8 + r4)*GPAD + kk + c4;
                uint32_t b0 = fbits(bp[0]), b1 = fbits(bp[4]);
                #pragma unroll
                for (int mi = 0; mi < 4; mi++)
                    mma_tf32(acc[mi][nj], af[mi][0], af[mi][1], af[mi][2], af[mi][3], b0, b1);
            }
        }
        __syncthreads();
    }

    #pragma unroll
    for (int mi = 0; mi < 4; mi++) {
        #pragma unroll
        for (int r2 = 0; r2 < 2; r2++) {
            int m = by*128 + wm + mi*16 + r4 + r2*8;
            int orow = permOut ? ((m & 1023)*B_ + (m >> 10)) : m;
            float* yp = Y + (size_t)orow*1024 + bx*128 + wn;
            const float* bi = bias + bx*128 + wn;
            #pragma unroll
            for (int nj = 0; nj < 4; nj++) {
                int c = nj*8 + 2*c4;
                float2 val;
                val.x = acc[mi][nj][r2*2 + 0] + bi[c];
                val.y = acc[mi][nj][r2*2 + 1] + bi[c + 1];
                if (roundOut) { val.x = tfround(val.x); val.y = tfround(val.y); }
                *(float2*)(yp + c) = val;
            }
        }
    }
}

__global__ void __launch_bounds__(256) tgemm_qkv(
    const float* __restrict__ bq, const float* __restrict__ bk,
    const float* __restrict__ bv, float* __restrict__ Y)
{
    __shared__ float As[2][GSTG];
    __shared__ float Bs[2][GSTG];
    int sel = blockIdx.z;
    const float* bi = (sel == 0) ? bq : (sel == 1) ? bk : bv;
    tgemm_body(g_xtf, g_wtf + (size_t)sel*E_*E_, bi, Y + (size_t)sel*B_*S_*E_,
               1, 0, sel == 2, blockIdx.x, blockIdx.y, As, Bs);
}

__global__ void __launch_bounds__(256) tgemm_wo(
    const float* __restrict__ bias, float* __restrict__ Y)
{
    __shared__ float As[2][GSTG];
    __shared__ float Bs[2][GSTG];
    tgemm_body(g_ctx, g_wtf + (size_t)3*E_*E_, bias, Y,
               0, 1, 0, blockIdx.x, blockIdx.y, As, Bs);
}

// ---------------------------------------------------------------------------
__global__ void gproj_kernel(const float* __restrict__ Wgq, const float* __restrict__ bgq,
                             const float* __restrict__ Wgk, const float* __restrict__ bgk)
{
    const float* Wg = blockIdx.y ? Wgk : Wgq;
    const float* bg = blockIdx.y ? bgk : bgq;
    float* out      = blockIdx.y ? g_gk : g_gq;
    int gw = (blockIdx.x * blockDim.x + threadIdx.x) >> 5;
    int lane = threadIdx.x & 31;
    int b = gw >> 10, o = gw & 1023;
    float acc = 0.f;
    #pragma unroll
    for (int e = lane * 4; e < E_; e += 128) {
        float4 gv = *(const float4*)&g_g[b*E_ + e];
        float4 wv = *(const float4*)&Wg[(size_t)o*E_ + e];
        acc += gv.x*wv.x + gv.y*wv.y + gv.z*wv.z + gv.w*wv.w;
    }
    #pragma unroll
    for (int of = 16; of; of >>= 1) acc += __shfl_xor_sync(0xffffffffu, acc, of);
    if (lane == 0) out[b*E_ + o] = acc + bg[o];
}

__global__ void gate_kernel(float* __restrict__ qkv,
                            const float* __restrict__ wvq, const float* __restrict__ bvq,
                            const float* __restrict__ wgq, const float* __restrict__ bgq,
                            const float* __restrict__ wvk, const float* __restrict__ bvk,
                            const float* __restrict__ wgk, const float* __restrict__ bgk)
{
    int z = blockIdx.y;
    float* buf        = qkv + (size_t)z * B_*S_*E_;
    const float* gbuf = z ? g_gk : g_gq;
    const float* wv   = z ? wvk : wvq;
    const float* bvp  = z ? bvk : bvq;
    const float* wg   = z ? wgk : wgq;
    const float* bgp  = z ? bgk : bgq;

    int gw   = (blockIdx.x * blockDim.x + threadIdx.x) >> 5;
    int lane = threadIdx.x & 31;
    int b = gw >> 14, h = (gw >> 10) & 15, s = gw & 1023;
    size_t off = ((size_t)(b*S_ + s))*E_ + h*D_;
    int goff = b*E_ + h*D_;
    float q0 = buf[off + lane],        q1 = buf[off + 32 + lane];
    float g0 = gbuf[goff + lane],      g1 = gbuf[goff + 32 + lane];
    float part = q0*wv[lane] + q1*wv[32 + lane] + g0*wg[lane] + g1*wg[32 + lane];
    #pragma unroll
    for (int o = 16; o; o >>= 1) part += __shfl_xor_sync(0xffffffffu, part, o);
    float alpha = 1.f / (1.f + __expf(-(part + bvp[0] + bgp[0])));
    buf[off + lane]      = tfround(q0 + alpha * (g0 - q0));
    buf[off + 32 + lane] = tfround(q1 + alpha * (g1 - q1));
}

// ---------------------------------------------------------------------------
// K1: raw scores = (Q @ K^T) * 0.125 written to p_out scratch.
// block = 128 q-rows x 128 keys, grid (8, 8, B*H). Single K=64 stage.
#define SPAD 68
#define SCORE_SMEM_BYTES (2 * 128 * SPAD * 4)

__global__ void __launch_bounds__(256) tscore_kernel(
    const float* __restrict__ q, const float* __restrict__ k,
    float* __restrict__ p_out)
{
    extern __shared__ float sm[];
    float* qa = sm;                 // [128][68]
    float* kb = sm + 128*SPAD;      // [128][68]

    const int bx = blockIdx.x, by = blockIdx.y, bh = blockIdx.z;
    const int b = bh >> 4, h = bh & 15;
    const int tid = threadIdx.x;
    const int lane = tid & 31, warp = tid >> 5;
    const int wm = (warp & 1) * 64, wn = (warp >> 1) * 32;
    const int r4 = lane >> 2, c4 = lane & 3;

    uint32_t qBase = (uint32_t)__cvta_generic_to_shared(qa);
    uint32_t kBase = (uint32_t)__cvta_generic_to_shared(kb);

    // 2 tiles x 128 rows x 16 float4 = 4096 cp16; 256 threads x 16 iters
    #pragma unroll
    for (int t = 0; t < 16; t++) {
        int idx = tid + t*256;
        int isK = idx >> 11;
        int r   = idx & 2047;
        int row = r >> 4, c16 = r & 15;
        const float* src = isK
            ? k + ((size_t)(b*S_ + bx*128 + row))*E_ + h*D_ + c16*4
            : q + ((size_t)(b*S_ + by*128 + row))*E_ + h*D_ + c16*4;
        uint32_t dst = (isK ? kBase : qBase) + (row*SPAD + c16*4)*4;
        cp16(dst, src);
    }
    asm volatile("cp.async.commit_group;" ::: "memory");
    asm volatile("cp.async.wait_group 0;" ::: "memory");
    __syncthreads();

    float acc[4][4][4];
    #pragma unroll
    for (int mi = 0; mi < 4; mi++)
        #pragma unroll
        for (int nj = 0; nj < 4; nj++)
            #pragma unroll
            for (int t = 0; t < 4; t++) acc[mi][nj][t] = 0.f;

    #pragma unroll
    for (int kk = 0; kk < 64; kk += 8) {
        uint32_t af[4][4];
        #pragma unroll
        for (int mi = 0; mi < 4; mi++) {
            const float* ap = qa + (wm + mi*16 + r4)*SPAD + kk + c4;
            af[mi][0] = fbits(ap[0]);
            af[mi][1] = fbits(ap[8*SPAD]);
            af[mi][2] = fbits(ap[4]);
            af[mi][3] = fbits(ap[8*SPAD + 4]);
        }
        #pragma unroll
        for (int nj = 0; nj < 4; nj++) {
            const float* bp = kb + (wn + nj*8 + r4)*SPAD + kk + c4;
            uint32_t b0 = fbits(bp[0]), b1 = fbits(bp[4]);
            #pragma unroll
            for (int mi = 0; mi < 4; mi++)
                mma_tf32(acc[mi][nj], af[mi][0], af[mi][1], af[mi][2], af[mi][3], b0, b1);
        }
    }

    float* pbase = p_out + ((size_t)bh << 20);
    #pragma unroll
    for (int mi = 0; mi < 4; mi++) {
        #pragma unroll
        for (int r2 = 0; r2 < 2; r2++) {
            int m = by*128 + wm + mi*16 + r4 + r2*8;
            float* yp = pbase + (size_t)m*1024 + bx*128 + wn;
            #pragma unroll
            for (int nj = 0; nj < 4; nj++) {
                int c = nj*8 + 2*c4;
                float2 val;
                val.x = acc[mi][nj][r2*2 + 0] * 0.125f;
                val.y = acc[mi][nj][r2*2 + 1] * 0.125f;
                *(float2*)(yp + c) = val;
            }
        }
    }
}

// ---------------------------------------------------------------------------
// K2: load raw score rows from p_out, softmax (mask), rewrite p_out normalized,
// then out = p @ v. V chunks double-buffered via cp.async.
#define SCP 1028
#define KVW 68
#define ATTN_SMEM_FLOATS (32*SCP + 2*64*KVW + 1024)
#define ATTN_SMEM_BYTES (ATTN_SMEM_FLOATS * 4)

__global__ void __launch_bounds__(256) attn2_kernel(
    const float* __restrict__ v, const int* __restrict__ mask,
    float* __restrict__ p_out, float* __restrict__ ctx)
{
    extern __shared__ float sm[];
    float* sc  = sm;                    // [32][1028]
    float* kvs = sc + 32*SCP;           // [2][64][68]
    float* mk  = kvs + 2*64*KVW;        // [1024]

    const int b = blockIdx.z, h = blockIdx.y, i0 = blockIdx.x * 32;
    const int tid = threadIdx.x;
    const int lane = tid & 31, warp = tid >> 5;
    const int r4 = lane >> 2, c4 = lane & 3;
    const int mi_w = warp & 1;
    const int njB  = (warp >> 1) * 2;

    uint32_t scBase = (uint32_t)__cvta_generic_to_shared(sc);
    uint32_t kvBase = (uint32_t)__cvta_generic_to_shared(kvs);

    float* prow0 = p_out + (((size_t)(b*H_ + h))*S_ + i0) * S_;

    auto issue_v = [&](int c) {
        int j0 = c * 64;
        uint32_t so = (uint32_t)((c & 1) * 64 * KVW * 4);
        #pragma unroll
        for (int t = 0; t < 4; t++) {
            int idx = tid + t*256;
            int j = idx >> 4, d4 = (idx & 15) * 4;
            cp16(kvBase + so + (j*KVW + d4)*4,
                 v + ((size_t)(b*S_ + j0 + j))*E_ + h*D_ + d4);
        }
        asm volatile("cp.async.commit_group;" ::: "memory");
    };

    // bulk-load 32 score rows: 32 x 256 float4 = 8192 cp16 (group 0)
    #pragma unroll
    for (int t = 0; t < 32; t++) {
        int idx = tid + t*256;
        int row = idx >> 8, ch = idx & 255;
        cp16(scBase + (row*SCP + ch*4)*4, prow0 + (size_t)row*S_ + ch*4);
    }
    asm volatile("cp.async.commit_group;" ::: "memory");

    issue_v(0);   // group 1

    for (int j = tid; j < S_; j += 256) mk[j] = (float)mask[b*S_ + j];

    asm volatile("cp.async.wait_group 1;" ::: "memory");  // scores done
    __syncthreads();

    // softmax + normalized p write (V chunk 0 in flight)
    for (int r = warp; r < 32; r += 8) {
        float* row = sc + r * SCP;
        float mx = -1e30f;
        for (int j = lane; j < 1024; j += 32) {
            float sv = (mk[j] != 0.f) ? row[j] : -1e9f;
            row[j] = sv;
            mx = fmaxf(mx, sv);
        }
        #pragma unroll
        for (int o = 16; o; o >>= 1) mx = fmaxf(mx, __shfl_xor_sync(0xffffffffu, mx, o));
        float sum = 0.f;
        for (int j = lane; j < 1024; j += 32) {
            float e = __expf(row[j] - mx);
            row[j] = e;
            sum += e;
        }
        #pragma unroll
        for (int o = 16; o; o >>= 1) sum += __shfl_xor_sync(0xffffffffu, sum, o);
        float inv = 1.f / sum;
        float* prow = prow0 + (size_t)r * S_;
        for (int j = lane; j < 1024; j += 32) {
            float pv = row[j] * inv;
            prow[j] = pv;              // fp32 p_attn output (in place)
            row[j] = tfround(pv);      // tf32 for PV A operand
        }
    }

    // out = p @ v
    float oacc[2][4] = {{0,0,0,0},{0,0,0,0}};
    for (int c = 0; c < 16; c++) {
        if (c < 15) {
            issue_v(c + 1);
            asm volatile("cp.async.wait_group 1;" ::: "memory");
        } else {
            asm volatile("cp.async.wait_group 0;" ::: "memory");
        }
        __syncthreads();
        const float* vc = kvs + (c & 1) * 64 * KVW;
        int j0 = c * 64;
        #pragma unroll
        for (int kk = 0; kk < 64; kk += 8) {
            const float* ap = sc + (mi_w*16 + r4)*SCP + j0 + kk + c4;
            uint32_t a0 = fbits(ap[0]), a1 = fbits(ap[8*SCP]);
            uint32_t a2 = fbits(ap[4]), a3 = fbits(ap[8*SCP + 4]);
            #pragma unroll
            for (int u = 0; u < 2; u++) {
                const float* bp = vc + (kk + c4)*KVW + (njB+u)*8 + r4;
                mma_tf32(oacc[u], a0, a1, a2, a3, fbits(bp[0]), fbits(bp[4*KVW]));
            }
        }
        __syncthreads();
    }
    {
        int r = mi_w*16 + r4;
        #pragma unroll
        for (int u = 0; u < 2; u++) {
            int cc = (njB+u)*8 + 2*c4;
            size_t o0 = ((size_t)(b*S_ + i0 + r))*E_ + h*D_ + cc;
            size_t o1 = ((size_t)(b*S_ + i0 + r + 8))*E_ + h*D_ + cc;
            *(float2*)&ctx[o0] = make_float2(tfround(oacc[u][0]), tfround(oacc[u][1]));
            *(float2*)&ctx[o1] = make_float2(tfround(oacc[u][2]), tfround(oacc[u][3]));
        }
    }
}

// ---------------------------------------------------------------------------
extern "C" void kernel_launch(void* const* d_in, const int* in_sizes, int n_in,
                              void* d_out, int out_size)
{
    const float* x    = (const float*)d_in[0];
    const int*   mask = (const int*)  d_in[1];
    const float* Wq = (const float*)d_in[2];
    const float* bq = (const float*)d_in[3];
    const float* Wk = (const float*)d_in[4];
    const float* bk = (const float*)d_in[5];
    const float* Wv = (const float*)d_in[6];
    const float* bv = (const float*)d_in[7];
    const float* Wo = (const float*)d_in[8];
    const float* bo = (const float*)d_in[9];
    const float* Wgq = (const float*)d_in[10];
    const float* bgq = (const float*)d_in[11];
    const float* Wgk = (const float*)d_in[12];
    const float* bgk = (const float*)d_in[13];
    const float* qg_wq = (const float*)d_in[14];
    const float* qg_bq = (const float*)d_in[15];
    const float* qg_wk = (const float*)d_in[16];
    const float* qg_bk = (const float*)d_in[17];
    const float* kg_wq = (const float*)d_in[18];
    const float* kg_bq = (const float*)d_in[19];
    const float* kg_wk = (const float*)d_in[20];
    const float* kg_bk = (const float*)d_in[21];

    float* out   = (float*)d_out;
    float* p_out = out + (size_t)S_ * B_ * E_;

    float *qkvb, *ctxb;
    cudaGetSymbolAddress((void**)&qkvb, g_qkv);
    cudaGetSymbolAddress((void**)&ctxb, g_ctx);
    float* qb = qkvb;
    float* kb = qkvb + (size_t)B_*S_*E_;
    float* vb = qkvb + 2*(size_t)B_*S_*E_;

    cudaFuncSetAttribute(tscore_kernel, cudaFuncAttributeMaxDynamicSharedMemorySize,
                         SCORE_SMEM_BYTES);
    cudaFuncSetAttribute(attn2_kernel, cudaFuncAttributeMaxDynamicSharedMemorySize,
                         ATTN_SMEM_BYTES);

    round_all<<<8192, 256>>>((const float4*)x, (const float4*)Wq,
                             (const float4*)Wk, (const float4*)Wv, (const float4*)Wo);
    msum_kernel<<<1, 128>>>(mask);
    mean_kernel<<<dim3(E_/64, B_), 256>>>(x, mask);

    tgemm_qkv<<<dim3(8, 32, 3), 256>>>(bq, bk, bv, qkvb);

    gproj_kernel<<<dim3(512, 2), 256>>>(Wgq, bgq, Wgk, bgk);

    gate_kernel<<<dim3(8192, 2), 256>>>(qkvb,
        qg_wq, qg_bq, qg_wk, qg_bk,
        kg_wq, kg_bq, kg_wk, kg_bk);

    tscore_kernel<<<dim3(8, 8, B_*H_), 256, SCORE_SMEM_BYTES>>>(qb, kb, p_out);

    attn2_kernel<<<dim3(S_/32, H_, B_), 256, ATTN_SMEM_BYTES>>>(
        vb, mask, p_out, ctxb);

    tgemm_wo<<<dim3(8, 32), 256>>>(bo, out);
}

// round 8
// speedup vs baseline: 1.0951x; 1.0951x over previous
#include <cuda_runtime.h>
#include <cstdint>

#define B_ 4
#define S_ 1024
#define E_ 1024
#define H_ 16
#define D_ 64

__device__ float g_qkv[3*B_*S_*E_];
__device__ float g_ctx[B_*S_*E_];
__device__ float g_xtf[B_*S_*E_];
__device__ float g_wtf[4*E_*E_];
__device__ float g_g[B_*E_];
__device__ float g_gq[B_*E_];
__device__ float g_gk[B_*E_];
__device__ float g_minv[B_];

__device__ __forceinline__ uint32_t fbits(float f) { return __float_as_uint(f); }

__device__ __forceinline__ uint32_t f2tf(float f) {
    uint32_t u;
    asm("cvt.rna.tf32.f32 %0, %1;" : "=r"(u) : "f"(f));
    return u;
}
__device__ __forceinline__ float tfround(float f) {
    return __uint_as_float(f2tf(f));
}

__device__ __forceinline__ void mma_tf32(float c[4],
    uint32_t a0, uint32_t a1, uint32_t a2, uint32_t a3,
    uint32_t b0, uint32_t b1)
{
    asm volatile(
        "mma.sync.aligned.m16n8k8.row.col.f32.tf32.tf32.f32 "
        "{%0,%1,%2,%3}, {%4,%5,%6,%7}, {%8,%9}, {%0,%1,%2,%3};"
        : "+f"(c[0]), "+f"(c[1]), "+f"(c[2]), "+f"(c[3])
        : "r"(a0), "r"(a1), "r"(a2), "r"(a3), "r"(b0), "r"(b1));
}

__device__ __forceinline__ void cp16(uint32_t saddr, const void* g) {
    asm volatile("cp.async.cg.shared.global [%0], [%1], 16;" :: "r"(saddr), "l"(g));
}

// ---------------------------------------------------------------------------
__global__ void __launch_bounds__(256) round_all(
    const float4* __restrict__ x,
    const float4* __restrict__ wq, const float4* __restrict__ wk,
    const float4* __restrict__ wv, const float4* __restrict__ wo)
{
    int idx = blockIdx.x * 256 + threadIdx.x;
    const float4* src;
    float4* dst;
    if (idx < (1 << 20)) {
        src = x + idx;
        dst = (float4*)g_xtf + idx;
    } else {
        int r = idx - (1 << 20);
        int w = r >> 18, o = r & ((1 << 18) - 1);
        const float4* s = (w == 0) ? wq : (w == 1) ? wk : (w == 2) ? wv : wo;
        src = s + o;
        dst = (float4*)g_wtf + ((size_t)w << 18) + o;
    }
    float4 v = *src;
    v.x = tfround(v.x); v.y = tfround(v.y);
    v.z = tfround(v.z); v.w = tfround(v.w);
    *dst = v;
}

// ---------------------------------------------------------------------------
__global__ void msum_kernel(const int* __restrict__ mask) {
    int b = threadIdx.x >> 5, lane = threadIdx.x & 31;
    float s = 0.f;
    for (int j = lane; j < S_; j += 32) s += (float)mask[b*S_ + j];
    #pragma unroll
    for (int o = 16; o; o >>= 1) s += __shfl_xor_sync(0xffffffffu, s, o);
    if (lane == 0) g_minv[b] = 1.0f / fmaxf(s, 1e-9f);
}

__global__ void mean_kernel(const float* __restrict__ x, const int* __restrict__ mask) {
    __shared__ float part[4][64];
    int b  = blockIdx.y;
    int e0 = blockIdx.x * 64;
    int el = threadIdx.x & 63, sq = threadIdx.x >> 6;
    float acc = 0.f;
    int sbeg = sq * 256;
    for (int s = sbeg; s < sbeg + 256; s++) {
        float m = (float)mask[b*S_ + s];
        acc += x[((size_t)s*B_ + b)*E_ + e0 + el] * m;
    }
    part[sq][el] = acc;
    __syncthreads();
    if (threadIdx.x < 64) {
        float t = part[0][el] + part[1][el] + part[2][el] + part[3][el];
        g_g[b*E_ + e0 + el] = t * g_minv[b];
    }
}

// ---------------------------------------------------------------------------
// tf32 GEMM core; inputs already tf32-rounded -> raw-bit fragment loads.
#define GPAD 20
#define GSTG (128*GPAD)

__device__ __forceinline__ void tgemm_body(
    const float* __restrict__ A, const float* __restrict__ W,
    const float* __restrict__ bias, float* __restrict__ Y,
    int permIn, int permOut, int roundOut, int bx, int by,
    float (*As)[GSTG], float (*Bs)[GSTG])
{
    const int tid = threadIdx.x;
    const int lane = tid & 31, warp = tid >> 5;
    const int wm = (warp & 1) * 64, wn = (warp >> 1) * 32;
    const int r4 = lane >> 2, c4 = lane & 3;

    uint32_t aBase = (uint32_t)__cvta_generic_to_shared(&As[0][0]);
    uint32_t bBase = (uint32_t)__cvta_generic_to_shared(&Bs[0][0]);

    int row0 = tid >> 2,         k40 = (tid & 3) * 4;
    int row1 = (tid + 256) >> 2, k41 = ((tid + 256) & 3) * 4;
    int am0 = by*128 + row0;
    int am1 = by*128 + row1;
    int ar0 = permIn ? ((am0 & 1023)*B_ + (am0 >> 10)) : am0;
    int ar1 = permIn ? ((am1 & 1023)*B_ + (am1 >> 10)) : am1;
    const float* ap0 = A + (size_t)ar0*1024 + k40;
    const float* ap1 = A + (size_t)ar1*1024 + k41;
    const float* wp0 = W + ((size_t)(bx*128 + row0))*1024 + k40;
    const float* wp1 = W + ((size_t)(bx*128 + row1))*1024 + k41;
    uint32_t ad0 = aBase + (row0*GPAD + k40)*4, ad1 = aBase + (row1*GPAD + k41)*4;
    uint32_t bd0 = bBase + (row0*GPAD + k40)*4, bd1 = bBase + (row1*GPAD + k41)*4;

    auto loadStage = [&](int stg, int k0) {
        uint32_t so = stg * GSTG * 4;
        cp16(ad0 + so, ap0 + k0);
        cp16(ad1 + so, ap1 + k0);
        cp16(bd0 + so, wp0 + k0);
        cp16(bd1 + so, wp1 + k0);
        asm volatile("cp.async.commit_group;" ::: "memory");
    };

    float acc[4][4][4];
    #pragma unroll
    for (int mi = 0; mi < 4; mi++)
        #pragma unroll
        for (int nj = 0; nj < 4; nj++)
            #pragma unroll
            for (int t = 0; t < 4; t++) acc[mi][nj][t] = 0.f;

    loadStage(0, 0);
    for (int ks = 0; ks < 64; ks++) {
        if (ks < 63) {
            loadStage((ks + 1) & 1, (ks + 1) * 16);
            asm volatile("cp.async.wait_group 1;" ::: "memory");
        } else {
            asm volatile("cp.async.wait_group 0;" ::: "memory");
        }
        __syncthreads();
        const float* as = As[ks & 1];
        const float* bs = Bs[ks & 1];
        #pragma unroll
        for (int kk = 0; kk < 16; kk += 8) {
            uint32_t af[4][4];
            #pragma unroll
            for (int mi = 0; mi < 4; mi++) {
                const float* ap = as + (wm + mi*16 + r4)*GPAD + kk + c4;
                af[mi][0] = fbits(ap[0]);
                af[mi][1] = fbits(ap[8*GPAD]);
                af[mi][2] = fbits(ap[4]);
                af[mi][3] = fbits(ap[8*GPAD + 4]);
            }
            #pragma unroll
            for (int nj = 0; nj < 4; nj++) {
                const float* bp = bs + (wn + nj*8 + r4)*GPAD + kk + c4;
                uint32_t b0 = fbits(bp[0]), b1 = fbits(bp[4]);
                #pragma unroll
                for (int mi = 0; mi < 4; mi++)
                    mma_tf32(acc[mi][nj], af[mi][0], af[mi][1], af[mi][2], af[mi][3], b0, b1);
            }
        }
        __syncthreads();
    }

    #pragma unroll
    for (int mi = 0; mi < 4; mi++) {
        #pragma unroll
        for (int r2 = 0; r2 < 2; r2++) {
            int m = by*128 + wm + mi*16 + r4 + r2*8;
            int orow = permOut ? ((m & 1023)*B_ + (m >> 10)) : m;
            float* yp = Y + (size_t)orow*1024 + bx*128 + wn;
            const float* bi = bias + bx*128 + wn;
            #pragma unroll
            for (int nj = 0; nj < 4; nj++) {
                int c = nj*8 + 2*c4;
                float2 val;
                val.x = acc[mi][nj][r2*2 + 0] + bi[c];
                val.y = acc[mi][nj][r2*2 + 1] + bi[c + 1];
                if (roundOut) { val.x = tfround(val.x); val.y = tfround(val.y); }
                *(float2*)(yp + c) = val;
            }
        }
    }
}

__global__ void __launch_bounds__(256) tgemm_qkv(
    const float* __restrict__ bq, const float* __restrict__ bk,
    const float* __restrict__ bv, float* __restrict__ Y)
{
    __shared__ float As[2][GSTG];
    __shared__ float Bs[2][GSTG];
    int sel = blockIdx.z;
    const float* bi = (sel == 0) ? bq : (sel == 1) ? bk : bv;
    tgemm_body(g_xtf, g_wtf + (size_t)sel*E_*E_, bi, Y + (size_t)sel*B_*S_*E_,
               1, 0, sel == 2, blockIdx.x, blockIdx.y, As, Bs);
}

__global__ void __launch_bounds__(256) tgemm_wo(
    const float* __restrict__ bias, float* __restrict__ Y)
{
    __shared__ float As[2][GSTG];
    __shared__ float Bs[2][GSTG];
    tgemm_body(g_ctx, g_wtf + (size_t)3*E_*E_, bias, Y,
               0, 1, 0, blockIdx.x, blockIdx.y, As, Bs);
}

// ---------------------------------------------------------------------------
__global__ void gproj_kernel(const float* __restrict__ Wgq, const float* __restrict__ bgq,
                             const float* __restrict__ Wgk, const float* __restrict__ bgk)
{
    const float* Wg = blockIdx.y ? Wgk : Wgq;
    const float* bg = blockIdx.y ? bgk : bgq;
    float* out      = blockIdx.y ? g_gk : g_gq;
    int gw = (blockIdx.x * blockDim.x + threadIdx.x) >> 5;
    int lane = threadIdx.x & 31;
    int b = gw >> 10, o = gw & 1023;
    float acc = 0.f;
    #pragma unroll
    for (int e = lane * 4; e < E_; e += 128) {
        float4 gv = *(const float4*)&g_g[b*E_ + e];
        float4 wv = *(const float4*)&Wg[(size_t)o*E_ + e];
        acc += gv.x*wv.x + gv.y*wv.y + gv.z*wv.z + gv.w*wv.w;
    }
    #pragma unroll
    for (int of = 16; of; of >>= 1) acc += __shfl_xor_sync(0xffffffffu, acc, of);
    if (lane == 0) out[b*E_ + o] = acc + bg[o];
}

__global__ void gate_kernel(float* __restrict__ qkv,
                            const float* __restrict__ wvq, const float* __restrict__ bvq,
                            const float* __restrict__ wgq, const float* __restrict__ bgq,
                            const float* __restrict__ wvk, const float* __restrict__ bvk,
                            const float* __restrict__ wgk, const float* __restrict__ bgk)
{
    int z = blockIdx.y;
    float* buf        = qkv + (size_t)z * B_*S_*E_;
    const float* gbuf = z ? g_gk : g_gq;
    const float* wv   = z ? wvk : wvq;
    const float* bvp  = z ? bvk : bvq;
    const float* wg   = z ? wgk : wgq;
    const float* bgp  = z ? bgk : bgq;

    int gw   = (blockIdx.x * blockDim.x + threadIdx.x) >> 5;
    int lane = threadIdx.x & 31;
    int b = gw >> 14, h = (gw >> 10) & 15, s = gw & 1023;
    size_t off = ((size_t)(b*S_ + s))*E_ + h*D_;
    int goff = b*E_ + h*D_;
    float q0 = buf[off + lane],        q1 = buf[off + 32 + lane];
    float g0 = gbuf[goff + lane],      g1 = gbuf[goff + 32 + lane];
    float part = q0*wv[lane] + q1*wv[32 + lane] + g0*wg[lane] + g1*wg[32 + lane];
    #pragma unroll
    for (int o = 16; o; o >>= 1) part += __shfl_xor_sync(0xffffffffu, part, o);
    float alpha = 1.f / (1.f + __expf(-(part + bvp[0] + bgp[0])));
    buf[off + lane]      = tfround(q0 + alpha * (g0 - q0));
    buf[off + 32 + lane] = tfround(q1 + alpha * (g1 - q1));
}

// ---------------------------------------------------------------------------
// fused attention, 128-key cp.async double-buffered chunks.
// All MMA operands pre-rounded to tf32 -> raw-bit loads only.
#define SCP 1028
#define KVW 68
#define CH 128
#define ATTN_SMEM_FLOATS (32*SCP + 32*KVW + 2*CH*KVW + 1024)
#define ATTN_SMEM_BYTES (ATTN_SMEM_FLOATS * 4)

__global__ void __launch_bounds__(256) attn_kernel(
    const float* __restrict__ q, const float* __restrict__ k,
    const float* __restrict__ v, const int* __restrict__ mask,
    float* __restrict__ p_out, float* __restrict__ ctx)
{
    extern __shared__ float sm[];
    float* sc  = sm;                    // [32][1028]
    float* qs  = sc + 32*SCP;           // [32][68]
    float* kvs = qs + 32*KVW;           // [2][128][68]
    float* mk  = kvs + 2*CH*KVW;        // [1024]

    const int b = blockIdx.z, h = blockIdx.y, i0 = blockIdx.x * 32;
    const int tid = threadIdx.x;
    const int lane = tid & 31, warp = tid >> 5;
    const int r4 = lane >> 2, c4 = lane & 3;
    const int mi_w = warp & 1;
    const int njw  = warp >> 1;          // phase1: 32-col group
    const int njB  = njw * 2;            // phase3: 2 n8 tiles

    uint32_t kvBase = (uint32_t)__cvta_generic_to_shared(kvs);

    // chunk c: 0..7 = K (128 keys each), 8..15 = V
    auto issue_chunk = [&](int c) {
        const float* src = (c < 8) ? k : v;
        int j0 = (c & 7) * CH;
        uint32_t so = (uint32_t)((c & 1) * CH * KVW * 4);
        #pragma unroll
        for (int t = 0; t < 8; t++) {
            int idx = tid + t*256;
            int j = idx >> 4, d4 = (idx & 15) * 4;
            cp16(kvBase + so + (j*KVW + d4)*4,
                 src + ((size_t)(b*S_ + j0 + j))*E_ + h*D_ + d4);
        }
        asm volatile("cp.async.commit_group;" ::: "memory");
    };

    issue_chunk(0);

    #pragma unroll
    for (int t = 0; t < 2; t++) {
        int idx = tid + t*256;
        int i = idx >> 4, d4 = (idx & 15) * 4;
        float4 qv = *(const float4*)&q[((size_t)(b*S_ + i0 + i))*E_ + h*D_ + d4];
        // q already tf32-rounded; *0.125 exact
        qv.x *= 0.125f; qv.y *= 0.125f; qv.z *= 0.125f; qv.w *= 0.125f;
        *(float4*)&qs[i*KVW + d4] = qv;
    }
    for (int j = tid; j < S_; j += 256) mk[j] = (float)mask[b*S_ + j];
    __syncthreads();

    // preload q A-fragments (32 regs)
    uint32_t qa[8][4];
    #pragma unroll
    for (int kk8 = 0; kk8 < 8; kk8++) {
        const float* ap = qs + (mi_w*16 + r4)*KVW + kk8*8 + c4;
        qa[kk8][0] = fbits(ap[0]);
        qa[kk8][1] = fbits(ap[8*KVW]);
        qa[kk8][2] = fbits(ap[4]);
        qa[kk8][3] = fbits(ap[8*KVW + 4]);
    }

    // ---- phase 1: scores = q @ k^T, 8 chunks of 128 keys ----
    for (int jt = 0; jt < 8; jt++) {
        issue_chunk(jt + 1);   // jt==7 prefetches V chunk 0
        asm volatile("cp.async.wait_group 1;" ::: "memory");
        __syncthreads();
        const float* kc = kvs + (jt & 1) * CH * KVW;

        float acc[4][4];
        #pragma unroll
        for (int u = 0; u < 4; u++)
            #pragma unroll
            for (int t = 0; t < 4; t++) acc[u][t] = 0.f;

        #pragma unroll
        for (int kk8 = 0; kk8 < 8; kk8++) {
            #pragma unroll
            for (int u = 0; u < 4; u++) {
                const float* bp = kc + (njw*32 + u*8 + r4)*KVW + kk8*8 + c4;
                mma_tf32(acc[u], qa[kk8][0], qa[kk8][1], qa[kk8][2], qa[kk8][3],
                         fbits(bp[0]), fbits(bp[4]));
            }
        }
        int j0 = jt * CH;
        int r  = mi_w*16 + r4;
        #pragma unroll
        for (int u = 0; u < 4; u++) {
            int n0 = j0 + njw*32 + u*8 + 2*c4;
            *(float2*)&sc[r*SCP + n0]     = make_float2(acc[u][0], acc[u][1]);
            *(float2*)&sc[(r+8)*SCP + n0] = make_float2(acc[u][2], acc[u][3]);
        }
        __syncthreads();
    }

    // ---- phase 2: softmax + streaming p write (V chunk 0 in flight) ----
    for (int r = warp; r < 32; r += 8) {
        float* row = sc + r * SCP;
        float mx = -1e30f;
        for (int j = lane; j < 1024; j += 32) {
            float sv = (mk[j] != 0.f) ? row[j] : -1e9f;
            row[j] = sv;
            mx = fmaxf(mx, sv);
        }
        #pragma unroll
        for (int o = 16; o; o >>= 1) mx = fmaxf(mx, __shfl_xor_sync(0xffffffffu, mx, o));
        float sum = 0.f;
        for (int j = lane; j < 1024; j += 32) {
            float e = __expf(row[j] - mx);
            row[j] = e;
            sum += e;
        }
        #pragma unroll
        for (int o = 16; o; o >>= 1) sum += __shfl_xor_sync(0xffffffffu, sum, o);
        float inv = 1.f / sum;
        float* prow = p_out + (((size_t)(b*H_ + h))*S_ + i0 + r) * S_;
        for (int j = lane; j < 1024; j += 32) {
            float pv = row[j] * inv;
            __stcs(prow + j, pv);      // streaming: don't evict V from L2
            row[j] = tfround(pv);      // tf32 for phase-3 A operand
        }
    }

    // ---- phase 3: out = p @ v, 8 chunks of 128 keys ----
    float oacc[2][4] = {{0,0,0,0},{0,0,0,0}};
    for (int c = 8; c < 16; c++) {
        if (c < 15) {
            issue_chunk(c + 1);
            asm volatile("cp.async.wait_group 1;" ::: "memory");
        } else {
            asm volatile("cp.async.wait_group 0;" ::: "memory");
        }
        __syncthreads();
        const float* vc = kvs + (c & 1) * CH * KVW;
        int j0 = (c - 8) * CH;
        #pragma unroll
        for (int kk = 0; kk < CH; kk += 8) {
            const float* ap = sc + (mi_w*16 + r4)*SCP + j0 + kk + c4;
            uint32_t a0 = fbits(ap[0]), a1 = fbits(ap[8*SCP]);
            uint32_t a2 = fbits(ap[4]), a3 = fbits(ap[8*SCP + 4]);
            #pragma unroll
            for (int u = 0; u < 2; u++) {
                const float* bp = vc + (kk + c4)*KVW + (njB+u)*8 + r4;
                mma_tf32(oacc[u], a0, a1, a2, a3, fbits(bp[0]), fbits(bp[4*KVW]));
            }
        }
        __syncthreads();
    }
    {
        int r = mi_w*16 + r4;
        #pragma unroll
        for (int u = 0; u < 2; u++) {
            int cc = (njB+u)*8 + 2*c4;
            size_t o0 = ((size_t)(b*S_ + i0 + r))*E_ + h*D_ + cc;
            size_t o1 = ((size_t)(b*S_ + i0 + r + 8))*E_ + h*D_ + cc;
            *(float2*)&ctx[o0] = make_float2(tfround(oacc[u][0]), tfround(oacc[u][1]));
            *(float2*)&ctx[o1] = make_float2(tfround(oacc[u][2]), tfround(oacc[u][3]));
        }
    }
}

// ---------------------------------------------------------------------------
extern "C" void kernel_launch(void* const* d_in, const int* in_sizes, int n_in,
                              void* d_out, int out_size)
{
    const float* x    = (const float*)d_in[0];
    const int*   mask = (const int*)  d_in[1];
    const float* Wq = (const float*)d_in[2];
    const float* bq = (const float*)d_in[3];
    const float* Wk = (const float*)d_in[4];
    const float* bk = (const float*)d_in[5];
    const float* Wv = (const float*)d_in[6];
    const float* bv = (const float*)d_in[7];
    const float* Wo = (const float*)d_in[8];
    const float* bo = (const float*)d_in[9];
    const float* Wgq = (const float*)d_in[10];
    const float* bgq = (const float*)d_in[11];
    const float* Wgk = (const float*)d_in[12];
    const float* bgk = (const float*)d_in[13];
    const float* qg_wq = (const float*)d_in[14];
    const float* qg_bq = (const float*)d_in[15];
    const float* qg_wk = (const float*)d_in[16];
    const float* qg_bk = (const float*)d_in[17];
    const float* kg_wq = (const float*)d_in[18];
    const float* kg_bq = (const float*)d_in[19];
    const float* kg_wk = (const float*)d_in[20];
    const float* kg_bk = (const float*)d_in[21];

    float* out   = (float*)d_out;
    float* p_out = out + (size_t)S_ * B_ * E_;

    float *qkvb, *ctxb;
    cudaGetSymbolAddress((void**)&qkvb, g_qkv);
    cudaGetSymbolAddress((void**)&ctxb, g_ctx);
    float* qb = qkvb;
    float* kb = qkvb + (size_t)B_*S_*E_;
    float* vb = qkvb + 2*(size_t)B_*S_*E_;

    cudaFuncSetAttribute(attn_kernel, cudaFuncAttributeMaxDynamicSharedMemorySize,
                         ATTN_SMEM_BYTES);

    round_all<<<8192, 256>>>((const float4*)x, (const float4*)Wq,
                             (const float4*)Wk, (const float4*)Wv, (const float4*)Wo);
    msum_kernel<<<1, 128>>>(mask);
    mean_kernel<<<dim3(E_/64, B_), 256>>>(x, mask);

    tgemm_qkv<<<dim3(8, 32, 3), 256>>>(bq, bk, bv, qkvb);

    gproj_kernel<<<dim3(512, 2), 256>>>(Wgq, bgq, Wgk, bgk);

    gate_kernel<<<dim3(8192, 2), 256>>>(qkvb,
        qg_wq, qg_bq, qg_wk, qg_bk,
        kg_wq, kg_bq, kg_wk, kg_bk);

    attn_kernel<<<dim3(S_/32, H_, B_), 256, ATTN_SMEM_BYTES>>>(
        qb, kb, vb, mask, p_out, ctxb);

    tgemm_wo<<<dim3(8, 32), 256>>>(bo, out);
}

// round 9
// speedup vs baseline: 1.1334x; 1.0350x over previous
#include <cuda_runtime.h>
#include <cstdint>

#define B_ 4
#define S_ 1024
#define E_ 1024
#define H_ 16
#define D_ 64

__device__ float g_qkv[3*B_*S_*E_];
__device__ float g_ctx[B_*S_*E_];
__device__ float g_xtf[B_*S_*E_];
__device__ float g_wtf[4*E_*E_];
__device__ float g_g[B_*E_];
__device__ float g_gq[B_*E_];
__device__ float g_gk[B_*E_];
__device__ float g_minv[B_];

__device__ __forceinline__ uint32_t fbits(float f) { return __float_as_uint(f); }

__device__ __forceinline__ uint32_t f2tf(float f) {
    uint32_t u;
    asm("cvt.rna.tf32.f32 %0, %1;" : "=r"(u) : "f"(f));
    return u;
}
__device__ __forceinline__ float tfround(float f) {
    return __uint_as_float(f2tf(f));
}

__device__ __forceinline__ void mma_tf32(float c[4],
    uint32_t a0, uint32_t a1, uint32_t a2, uint32_t a3,
    uint32_t b0, uint32_t b1)
{
    asm volatile(
        "mma.sync.aligned.m16n8k8.row.col.f32.tf32.tf32.f32 "
        "{%0,%1,%2,%3}, {%4,%5,%6,%7}, {%8,%9}, {%0,%1,%2,%3};"
        : "+f"(c[0]), "+f"(c[1]), "+f"(c[2]), "+f"(c[3])
        : "r"(a0), "r"(a1), "r"(a2), "r"(a3), "r"(b0), "r"(b1));
}

__device__ __forceinline__ void cp16(uint32_t saddr, const void* g) {
    asm volatile("cp.async.cg.shared.global [%0], [%1], 16;" :: "r"(saddr), "l"(g));
}

// ---------------------------------------------------------------------------
__global__ void __launch_bounds__(256) round_all(
    const float4* __restrict__ x,
    const float4* __restrict__ wq, const float4* __restrict__ wk,
    const float4* __restrict__ wv, const float4* __restrict__ wo)
{
    int idx = blockIdx.x * 256 + threadIdx.x;
    const float4* src;
    float4* dst;
    if (idx < (1 << 20)) {
        src = x + idx;
        dst = (float4*)g_xtf + idx;
    } else {
        int r = idx - (1 << 20);
        int w = r >> 18, o = r & ((1 << 18) - 1);
        const float4* s = (w == 0) ? wq : (w == 1) ? wk : (w == 2) ? wv : wo;
        src = s + o;
        dst = (float4*)g_wtf + ((size_t)w << 18) + o;
    }
    float4 v = *src;
    v.x = tfround(v.x); v.y = tfround(v.y);
    v.z = tfround(v.z); v.w = tfround(v.w);
    *dst = v;
}

// ---------------------------------------------------------------------------
__global__ void msum_kernel(const int* __restrict__ mask) {
    int b = threadIdx.x >> 5, lane = threadIdx.x & 31;
    float s = 0.f;
    for (int j = lane; j < S_; j += 32) s += (float)mask[b*S_ + j];
    #pragma unroll
    for (int o = 16; o; o >>= 1) s += __shfl_xor_sync(0xffffffffu, s, o);
    if (lane == 0) g_minv[b] = 1.0f / fmaxf(s, 1e-9f);
}

__global__ void mean_kernel(const float* __restrict__ x, const int* __restrict__ mask) {
    __shared__ float part[4][64];
    int b  = blockIdx.y;
    int e0 = blockIdx.x * 64;
    int el = threadIdx.x & 63, sq = threadIdx.x >> 6;
    float acc = 0.f;
    int sbeg = sq * 256;
    for (int s = sbeg; s < sbeg + 256; s++) {
        float m = (float)mask[b*S_ + s];
        acc += x[((size_t)s*B_ + b)*E_ + e0 + el] * m;
    }
    part[sq][el] = acc;
    __syncthreads();
    if (threadIdx.x < 64) {
        float t = part[0][el] + part[1][el] + part[2][el] + part[3][el];
        g_g[b*E_ + e0 + el] = t * g_minv[b];
    }
}

// ---------------------------------------------------------------------------
// tf32 GEMM core; inputs already tf32-rounded -> raw-bit fragment loads.
#define GPAD 20
#define GSTG (128*GPAD)

__device__ __forceinline__ void tgemm_body(
    const float* __restrict__ A, const float* __restrict__ W,
    const float* __restrict__ bias, float* __restrict__ Y,
    int permIn, int permOut, int roundOut, int bx, int by,
    float (*As)[GSTG], float (*Bs)[GSTG])
{
    const int tid = threadIdx.x;
    const int lane = tid & 31, warp = tid >> 5;
    const int wm = (warp & 1) * 64, wn = (warp >> 1) * 32;
    const int r4 = lane >> 2, c4 = lane & 3;

    uint32_t aBase = (uint32_t)__cvta_generic_to_shared(&As[0][0]);
    uint32_t bBase = (uint32_t)__cvta_generic_to_shared(&Bs[0][0]);

    int row0 = tid >> 2,         k40 = (tid & 3) * 4;
    int row1 = (tid + 256) >> 2, k41 = ((tid + 256) & 3) * 4;
    int am0 = by*128 + row0;
    int am1 = by*128 + row1;
    int ar0 = permIn ? ((am0 & 1023)*B_ + (am0 >> 10)) : am0;
    int ar1 = permIn ? ((am1 & 1023)*B_ + (am1 >> 10)) : am1;
    const float* ap0 = A + (size_t)ar0*1024 + k40;
    const float* ap1 = A + (size_t)ar1*1024 + k41;
    const float* wp0 = W + ((size_t)(bx*128 + row0))*1024 + k40;
    const float* wp1 = W + ((size_t)(bx*128 + row1))*1024 + k41;
    uint32_t ad0 = aBase + (row0*GPAD + k40)*4, ad1 = aBase + (row1*GPAD + k41)*4;
    uint32_t bd0 = bBase + (row0*GPAD + k40)*4, bd1 = bBase + (row1*GPAD + k41)*4;

    auto loadStage = [&](int stg, int k0) {
        uint32_t so = stg * GSTG * 4;
        cp16(ad0 + so, ap0 + k0);
        cp16(ad1 + so, ap1 + k0);
        cp16(bd0 + so, wp0 + k0);
        cp16(bd1 + so, wp1 + k0);
        asm volatile("cp.async.commit_group;" ::: "memory");
    };

    float acc[4][4][4];
    #pragma unroll
    for (int mi = 0; mi < 4; mi++)
        #pragma unroll
        for (int nj = 0; nj < 4; nj++)
            #pragma unroll
            for (int t = 0; t < 4; t++) acc[mi][nj][t] = 0.f;

    loadStage(0, 0);
    for (int ks = 0; ks < 64; ks++) {
        if (ks < 63) {
            loadStage((ks + 1) & 1, (ks + 1) * 16);
            asm volatile("cp.async.wait_group 1;" ::: "memory");
        } else {
            asm volatile("cp.async.wait_group 0;" ::: "memory");
        }
        __syncthreads();
        const float* as = As[ks & 1];
        const float* bs = Bs[ks & 1];
        #pragma unroll
        for (int kk = 0; kk < 16; kk += 8) {
            uint32_t af[4][4];
            #pragma unroll
            for (int mi = 0; mi < 4; mi++) {
                const float* ap = as + (wm + mi*16 + r4)*GPAD + kk + c4;
                af[mi][0] = fbits(ap[0]);
                af[mi][1] = fbits(ap[8*GPAD]);
                af[mi][2] = fbits(ap[4]);
                af[mi][3] = fbits(ap[8*GPAD + 4]);
            }
            #pragma unroll
            for (int nj = 0; nj < 4; nj++) {
                const float* bp = bs + (wn + nj*8 + r4)*GPAD + kk + c4;
                uint32_t b0 = fbits(bp[0]), b1 = fbits(bp[4]);
                #pragma unroll
                for (int mi = 0; mi < 4; mi++)
                    mma_tf32(acc[mi][nj], af[mi][0], af[mi][1], af[mi][2], af[mi][3], b0, b1);
            }
        }
        __syncthreads();
    }

    #pragma unroll
    for (int mi = 0; mi < 4; mi++) {
        #pragma unroll
        for (int r2 = 0; r2 < 2; r2++) {
            int m = by*128 + wm + mi*16 + r4 + r2*8;
            int orow = permOut ? ((m & 1023)*B_ + (m >> 10)) : m;
            float* yp = Y + (size_t)orow*1024 + bx*128 + wn;
            const float* bi = bias + bx*128 + wn;
            #pragma unroll
            for (int nj = 0; nj < 4; nj++) {
                int c = nj*8 + 2*c4;
                float2 val;
                val.x = acc[mi][nj][r2*2 + 0] + bi[c];
                val.y = acc[mi][nj][r2*2 + 1] + bi[c + 1];
                if (roundOut) { val.x = tfround(val.x); val.y = tfround(val.y); }
                *(float2*)(yp + c) = val;
            }
        }
    }
}

__global__ void __launch_bounds__(256) tgemm_qkv(
    const float* __restrict__ bq, const float* __restrict__ bk,
    const float* __restrict__ bv, float* __restrict__ Y)
{
    __shared__ float As[2][GSTG];
    __shared__ float Bs[2][GSTG];
    int sel = blockIdx.z;
    const float* bi = (sel == 0) ? bq : (sel == 1) ? bk : bv;
    tgemm_body(g_xtf, g_wtf + (size_t)sel*E_*E_, bi, Y + (size_t)sel*B_*S_*E_,
               1, 0, sel == 2, blockIdx.x, blockIdx.y, As, Bs);
}

__global__ void __launch_bounds__(256) tgemm_wo(
    const float* __restrict__ bias, float* __restrict__ Y)
{
    __shared__ float As[2][GSTG];
    __shared__ float Bs[2][GSTG];
    tgemm_body(g_ctx, g_wtf + (size_t)3*E_*E_, bias, Y,
               0, 1, 0, blockIdx.x, blockIdx.y, As, Bs);
}

// ---------------------------------------------------------------------------
__global__ void gproj_kernel(const float* __restrict__ Wgq, const float* __restrict__ bgq,
                             const float* __restrict__ Wgk, const float* __restrict__ bgk)
{
    const float* Wg = blockIdx.y ? Wgk : Wgq;
    const float* bg = blockIdx.y ? bgk : bgq;
    float* out      = blockIdx.y ? g_gk : g_gq;
    int gw = (blockIdx.x * blockDim.x + threadIdx.x) >> 5;
    int lane = threadIdx.x & 31;
    int b = gw >> 10, o = gw & 1023;
    float acc = 0.f;
    #pragma unroll
    for (int e = lane * 4; e < E_; e += 128) {
        float4 gv = *(const float4*)&g_g[b*E_ + e];
        float4 wv = *(const float4*)&Wg[(size_t)o*E_ + e];
        acc += gv.x*wv.x + gv.y*wv.y + gv.z*wv.z + gv.w*wv.w;
    }
    #pragma unroll
    for (int of = 16; of; of >>= 1) acc += __shfl_xor_sync(0xffffffffu, acc, of);
    if (lane == 0) out[b*E_ + o] = acc + bg[o];
}

__global__ void gate_kernel(float* __restrict__ qkv,
                            const float* __restrict__ wvq, const float* __restrict__ bvq,
                            const float* __restrict__ wgq, const float* __restrict__ bgq,
                            const float* __restrict__ wvk, const float* __restrict__ bvk,
                            const float* __restrict__ wgk, const float* __restrict__ bgk)
{
    int z = blockIdx.y;
    float* buf        = qkv + (size_t)z * B_*S_*E_;
    const float* gbuf = z ? g_gk : g_gq;
    const float* wv   = z ? wvk : wvq;
    const float* bvp  = z ? bvk : bvq;
    const float* wg   = z ? wgk : wgq;
    const float* bgp  = z ? bgk : bgq;

    int gw   = (blockIdx.x * blockDim.x + threadIdx.x) >> 5;
    int lane = threadIdx.x & 31;
    int b = gw >> 14, h = (gw >> 10) & 15, s = gw & 1023;
    size_t off = ((size_t)(b*S_ + s))*E_ + h*D_;
    int goff = b*E_ + h*D_;
    float q0 = buf[off + lane],        q1 = buf[off + 32 + lane];
    float g0 = gbuf[goff + lane],      g1 = gbuf[goff + 32 + lane];
    float part = q0*wv[lane] + q1*wv[32 + lane] + g0*wg[lane] + g1*wg[32 + lane];
    #pragma unroll
    for (int o = 16; o; o >>= 1) part += __shfl_xor_sync(0xffffffffu, part, o);
    float alpha = 1.f / (1.f + __expf(-(part + bvp[0] + bgp[0])));
    buf[off + lane]      = tfround(q0 + alpha * (g0 - q0));
    buf[off + 32 + lane] = tfround(q1 + alpha * (g1 - q1));
}

// ---------------------------------------------------------------------------
// fused attention: 16 q-rows/CTA (2 CTA/SM), cp.async double-buffered 64-key
// chunks. K chunks stride 68 (phase-1 conflict-free); V chunks stride 72
// (phase-3 conflict-free). All MMA operands pre-rounded tf32 -> raw-bit loads.
#define SCP 1028
#define KW 68
#define VW 72
#define ATTN_SMEM_FLOATS (16*SCP + 16*KW + 2*64*VW + 1024)
#define ATTN_SMEM_BYTES (ATTN_SMEM_FLOATS * 4)

__global__ void __launch_bounds__(256) attn_kernel(
    const float* __restrict__ q, const float* __restrict__ k,
    const float* __restrict__ v, const int* __restrict__ mask,
    float* __restrict__ p_out, float* __restrict__ ctx)
{
    extern __shared__ float sm[];
    float* sc  = sm;                    // [16][1028]
    float* qs  = sc + 16*SCP;           // [16][68]
    float* kvs = qs + 16*KW;            // [2][64][72] (K uses 68 stride inside)
    float* mk  = kvs + 2*64*VW;         // [1024]

    const int b = blockIdx.z, h = blockIdx.y, i0 = blockIdx.x * 16;
    const int tid = threadIdx.x;
    const int lane = tid & 31, warp = tid >> 5;
    const int r4 = lane >> 2, c4 = lane & 3;

    uint32_t kvBase = (uint32_t)__cvta_generic_to_shared(kvs);

    // chunk c: 0..15 = K (stride 68), 16..31 = V (stride 72)
    auto issue_chunk = [&](int c) {
        const float* src = (c < 16) ? k : v;
        int stride = (c < 16) ? KW : VW;
        int j0 = (c & 15) * 64;
        uint32_t so = (uint32_t)((c & 1) * 64 * VW * 4);
        #pragma unroll
        for (int t = 0; t < 4; t++) {
            int idx = tid + t*256;
            int j = idx >> 4, d4 = (idx & 15) * 4;
            cp16(kvBase + so + (j*stride + d4)*4,
                 src + ((size_t)(b*S_ + j0 + j))*E_ + h*D_ + d4);
        }
        asm volatile("cp.async.commit_group;" ::: "memory");
    };

    issue_chunk(0);

    {
        int i = tid >> 4, d4 = (tid & 15) * 4;
        float4 qv = *(const float4*)&q[((size_t)(b*S_ + i0 + i))*E_ + h*D_ + d4];
        qv.x *= 0.125f; qv.y *= 0.125f; qv.z *= 0.125f; qv.w *= 0.125f;
        *(float4*)&qs[i*KW + d4] = qv;
    }
    for (int j = tid; j < S_; j += 256) mk[j] = (float)mask[b*S_ + j];
    __syncthreads();

    // preload q A-fragments (32 regs, rows 0-15)
    uint32_t qa[8][4];
    #pragma unroll
    for (int kk8 = 0; kk8 < 8; kk8++) {
        const float* ap = qs + r4*KW + kk8*8 + c4;
        qa[kk8][0] = fbits(ap[0]);
        qa[kk8][1] = fbits(ap[8*KW]);
        qa[kk8][2] = fbits(ap[4]);
        qa[kk8][3] = fbits(ap[8*KW + 4]);
    }

    // ---- phase 1: scores = q @ k^T, 16 chunks of 64 keys, warp = n8 tile ----
    for (int jt = 0; jt < 16; jt++) {
        issue_chunk(jt + 1);   // jt==15 prefetches V chunk 0
        asm volatile("cp.async.wait_group 1;" ::: "memory");
        __syncthreads();
        const float* kc = kvs + (jt & 1) * 64 * VW;

        float acc[4] = {0,0,0,0};
        #pragma unroll
        for (int kk8 = 0; kk8 < 8; kk8++) {
            const float* bp = kc + (warp*8 + r4)*KW + kk8*8 + c4;
            mma_tf32(acc, qa[kk8][0], qa[kk8][1], qa[kk8][2], qa[kk8][3],
                     fbits(bp[0]), fbits(bp[4]));
        }
        int n0 = jt*64 + warp*8 + 2*c4;
        *(float2*)&sc[r4*SCP + n0]     = make_float2(acc[0], acc[1]);
        *(float2*)&sc[(r4+8)*SCP + n0] = make_float2(acc[2], acc[3]);
        __syncthreads();
    }

    // ---- phase 2: softmax + streaming p write (V chunk 0 in flight) ----
    for (int r = warp; r < 16; r += 8) {
        float* row = sc + r * SCP;
        float mx = -1e30f;
        for (int j = lane; j < 1024; j += 32) {
            float sv = (mk[j] != 0.f) ? row[j] : -1e9f;
            row[j] = sv;
            mx = fmaxf(mx, sv);
        }
        #pragma unroll
        for (int o = 16; o; o >>= 1) mx = fmaxf(mx, __shfl_xor_sync(0xffffffffu, mx, o));
        float sum = 0.f;
        for (int j = lane; j < 1024; j += 32) {
            float e = __expf(row[j] - mx);
            row[j] = e;
            sum += e;
        }
        #pragma unroll
        for (int o = 16; o; o >>= 1) sum += __shfl_xor_sync(0xffffffffu, sum, o);
        float inv = 1.f / sum;
        float* prow = p_out + (((size_t)(b*H_ + h))*S_ + i0 + r) * S_;
        for (int j = lane; j < 1024; j += 32) {
            float pv = row[j] * inv;
            __stcs(prow + j, pv);      // streaming: don't evict V from L2
            row[j] = tfround(pv);      // tf32 for phase-3 A operand
        }
    }

    // ---- phase 3: out = p @ v, warp = n8 tile of d ----
    float oacc[4] = {0,0,0,0};
    for (int c = 16; c < 32; c++) {
        if (c < 31) {
            issue_chunk(c + 1);
            asm volatile("cp.async.wait_group 1;" ::: "memory");
        } else {
            asm volatile("cp.async.wait_group 0;" ::: "memory");
        }
        __syncthreads();
        const float* vc = kvs + (c & 1) * 64 * VW;
        int j0 = (c - 16) * 64;
        #pragma unroll
        for (int kk = 0; kk < 64; kk += 8) {
            const float* ap = sc + r4*SCP + j0 + kk + c4;
            uint32_t a0 = fbits(ap[0]), a1 = fbits(ap[8*SCP]);
            uint32_t a2 = fbits(ap[4]), a3 = fbits(ap[8*SCP + 4]);
            const float* bp = vc + (kk + c4)*VW + warp*8 + r4;
            mma_tf32(oacc, a0, a1, a2, a3, fbits(bp[0]), fbits(bp[4*VW]));
        }
        __syncthreads();
    }
    {
        int cc = warp*8 + 2*c4;
        size_t o0 = ((size_t)(b*S_ + i0 + r4))*E_ + h*D_ + cc;
        size_t o1 = ((size_t)(b*S_ + i0 + r4 + 8))*E_ + h*D_ + cc;
        *(float2*)&ctx[o0] = make_float2(tfround(oacc[0]), tfround(oacc[1]));
        *(float2*)&ctx[o1] = make_float2(tfround(oacc[2]), tfround(oacc[3]));
    }
}

// ---------------------------------------------------------------------------
extern "C" void kernel_launch(void* const* d_in, const int* in_sizes, int n_in,
                              void* d_out, int out_size)
{
    const float* x    = (const float*)d_in[0];
    const int*   mask = (const int*)  d_in[1];
    const float* Wq = (const float*)d_in[2];
    const float* bq = (const float*)d_in[3];
    const float* Wk = (const float*)d_in[4];
    const float* bk = (const float*)d_in[5];
    const float* Wv = (const float*)d_in[6];
    const float* bv = (const float*)d_in[7];
    const float* Wo = (const float*)d_in[8];
    const float* bo = (const float*)d_in[9];
    const float* Wgq = (const float*)d_in[10];
    const float* bgq = (const float*)d_in[11];
    const float* Wgk = (const float*)d_in[12];
    const float* bgk = (const float*)d_in[13];
    const float* qg_wq = (const float*)d_in[14];
    const float* qg_bq = (const float*)d_in[15];
    const float* qg_wk = (const float*)d_in[16];
    const float* qg_bk = (const float*)d_in[17];
    const float* kg_wq = (const float*)d_in[18];
    const float* kg_bq = (const float*)d_in[19];
    const float* kg_wk = (const float*)d_in[20];
    const float* kg_bk = (const float*)d_in[21];

    float* out   = (float*)d_out;
    float* p_out = out + (size_t)S_ * B_ * E_;

    float *qkvb, *ctxb;
    cudaGetSymbolAddress((void**)&qkvb, g_qkv);
    cudaGetSymbolAddress((void**)&ctxb, g_ctx);
    float* qb = qkvb;
    float* kb = qkvb + (size_t)B_*S_*E_;
    float* vb = qkvb + 2*(size_t)B_*S_*E_;

    cudaFuncSetAttribute(attn_kernel, cudaFuncAttributeMaxDynamicSharedMemorySize,
                         ATTN_SMEM_BYTES);

    round_all<<<8192, 256>>>((const float4*)x, (const float4*)Wq,
                             (const float4*)Wk, (const float4*)Wv, (const float4*)Wo);
    msum_kernel<<<1, 128>>>(mask);
    mean_kernel<<<dim3(E_/64, B_), 256>>>(x, mask);

    tgemm_qkv<<<dim3(8, 32, 3), 256>>>(bq, bk, bv, qkvb);

    gproj_kernel<<<dim3(512, 2), 256>>>(Wgq, bgq, Wgk, bgk);

    gate_kernel<<<dim3(8192, 2), 256>>>(qkvb,
        qg_wq, qg_bq, qg_wk, qg_bk,
        kg_wq, kg_bq, kg_wk, kg_bk);

    attn_kernel<<<dim3(S_/16, H_, B_), 256, ATTN_SMEM_BYTES>>>(
        qb, kb, vb, mask, p_out, ctxb);

    tgemm_wo<<<dim3(8, 32), 256>>>(bo, out);
}

// round 10
// speedup vs baseline: 1.1849x; 1.0454x over previous
#include <cuda_runtime.h>
#include <cstdint>

#define B_ 4
#define S_ 1024
#define E_ 1024
#define H_ 16
#define D_ 64

__device__ float g_qkv[3*B_*S_*E_];
__device__ float g_ctx[B_*S_*E_];
__device__ float g_xtf[B_*S_*E_];
__device__ float g_wtf[4*E_*E_];
__device__ float g_g[B_*E_];
__device__ float g_gq[B_*E_];
__device__ float g_gk[B_*E_];
__device__ float g_minv[B_];

__device__ __forceinline__ uint32_t fbits(float f) { return __float_as_uint(f); }

__device__ __forceinline__ uint32_t f2tf(float f) {
    uint32_t u;
    asm("cvt.rna.tf32.f32 %0, %1;" : "=r"(u) : "f"(f));
    return u;
}
__device__ __forceinline__ float tfround(float f) {
    return __uint_as_float(f2tf(f));
}

__device__ __forceinline__ void mma_tf32(float c[4],
    uint32_t a0, uint32_t a1, uint32_t a2, uint32_t a3,
    uint32_t b0, uint32_t b1)
{
    asm volatile(
        "mma.sync.aligned.m16n8k8.row.col.f32.tf32.tf32.f32 "
        "{%0,%1,%2,%3}, {%4,%5,%6,%7}, {%8,%9}, {%0,%1,%2,%3};"
        : "+f"(c[0]), "+f"(c[1]), "+f"(c[2]), "+f"(c[3])
        : "r"(a0), "r"(a1), "r"(a2), "r"(a3), "r"(b0), "r"(b1));
}

__device__ __forceinline__ void cp16(uint32_t saddr, const void* g) {
    asm volatile("cp.async.cg.shared.global [%0], [%1], 16;" :: "r"(saddr), "l"(g));
}

// ---------------------------------------------------------------------------
__global__ void __launch_bounds__(256) round_all(
    const float4* __restrict__ x,
    const float4* __restrict__ wq, const float4* __restrict__ wk,
    const float4* __restrict__ wv, const float4* __restrict__ wo)
{
    int idx = blockIdx.x * 256 + threadIdx.x;
    const float4* src;
    float4* dst;
    if (idx < (1 << 20)) {
        src = x + idx;
        dst = (float4*)g_xtf + idx;
    } else {
        int r = idx - (1 << 20);
        int w = r >> 18, o = r & ((1 << 18) - 1);
        const float4* s = (w == 0) ? wq : (w == 1) ? wk : (w == 2) ? wv : wo;
        src = s + o;
        dst = (float4*)g_wtf + ((size_t)w << 18) + o;
    }
    float4 v = *src;
    v.x = tfround(v.x); v.y = tfround(v.y);
    v.z = tfround(v.z); v.w = tfround(v.w);
    *dst = v;
}

// ---------------------------------------------------------------------------
__global__ void msum_kernel(const int* __restrict__ mask) {
    int b = threadIdx.x >> 5, lane = threadIdx.x & 31;
    float s = 0.f;
    for (int j = lane; j < S_; j += 32) s += (float)mask[b*S_ + j];
    #pragma unroll
    for (int o = 16; o; o >>= 1) s += __shfl_xor_sync(0xffffffffu, s, o);
    if (lane == 0) g_minv[b] = 1.0f / fmaxf(s, 1e-9f);
}

__global__ void mean_kernel(const float* __restrict__ x, const int* __restrict__ mask) {
    __shared__ float part[4][64];
    int b  = blockIdx.y;
    int e0 = blockIdx.x * 64;
    int el = threadIdx.x & 63, sq = threadIdx.x >> 6;
    float acc = 0.f;
    int sbeg = sq * 256;
    for (int s = sbeg; s < sbeg + 256; s++) {
        float m = (float)mask[b*S_ + s];
        acc += x[((size_t)s*B_ + b)*E_ + e0 + el] * m;
    }
    part[sq][el] = acc;
    __syncthreads();
    if (threadIdx.x < 64) {
        float t = part[0][el] + part[1][el] + part[2][el] + part[3][el];
        g_g[b*E_ + e0 + el] = t * g_minv[b];
    }
}

// ---------------------------------------------------------------------------
// tf32 GEMM core; inputs already tf32-rounded -> raw-bit fragment loads.
#define GPAD 20
#define GSTG (128*GPAD)

__device__ __forceinline__ void tgemm_body(
    const float* __restrict__ A, const float* __restrict__ W,
    const float* __restrict__ bias, float* __restrict__ Y,
    int permIn, int permOut, int roundOut, int bx, int by,
    float (*As)[GSTG], float (*Bs)[GSTG])
{
    const int tid = threadIdx.x;
    const int lane = tid & 31, warp = tid >> 5;
    const int wm = (warp & 1) * 64, wn = (warp >> 1) * 32;
    const int r4 = lane >> 2, c4 = lane & 3;

    uint32_t aBase = (uint32_t)__cvta_generic_to_shared(&As[0][0]);
    uint32_t bBase = (uint32_t)__cvta_generic_to_shared(&Bs[0][0]);

    int row0 = tid >> 2,         k40 = (tid & 3) * 4;
    int row1 = (tid + 256) >> 2, k41 = ((tid + 256) & 3) * 4;
    int am0 = by*128 + row0;
    int am1 = by*128 + row1;
    int ar0 = permIn ? ((am0 & 1023)*B_ + (am0 >> 10)) : am0;
    int ar1 = permIn ? ((am1 & 1023)*B_ + (am1 >> 10)) : am1;
    const float* ap0 = A + (size_t)ar0*1024 + k40;
    const float* ap1 = A + (size_t)ar1*1024 + k41;
    const float* wp0 = W + ((size_t)(bx*128 + row0))*1024 + k40;
    const float* wp1 = W + ((size_t)(bx*128 + row1))*1024 + k41;
    uint32_t ad0 = aBase + (row0*GPAD + k40)*4, ad1 = aBase + (row1*GPAD + k41)*4;
    uint32_t bd0 = bBase + (row0*GPAD + k40)*4, bd1 = bBase + (row1*GPAD + k41)*4;

    auto loadStage = [&](int stg, int k0) {
        uint32_t so = stg * GSTG * 4;
        cp16(ad0 + so, ap0 + k0);
        cp16(ad1 + so, ap1 + k0);
        cp16(bd0 + so, wp0 + k0);
        cp16(bd1 + so, wp1 + k0);
        asm volatile("cp.async.commit_group;" ::: "memory");
    };

    float acc[4][4][4];
    #pragma unroll
    for (int mi = 0; mi < 4; mi++)
        #pragma unroll
        for (int nj = 0; nj < 4; nj++)
            #pragma unroll
            for (int t = 0; t < 4; t++) acc[mi][nj][t] = 0.f;

    loadStage(0, 0);
    for (int ks = 0; ks < 64; ks++) {
        if (ks < 63) {
            loadStage((ks + 1) & 1, (ks + 1) * 16);
            asm volatile("cp.async.wait_group 1;" ::: "memory");
        } else {
            asm volatile("cp.async.wait_group 0;" ::: "memory");
        }
        __syncthreads();
        const float* as = As[ks & 1];
        const float* bs = Bs[ks & 1];
        #pragma unroll
        for (int kk = 0; kk < 16; kk += 8) {
            uint32_t af[4][4];
            #pragma unroll
            for (int mi = 0; mi < 4; mi++) {
                const float* ap = as + (wm + mi*16 + r4)*GPAD + kk + c4;
                af[mi][0] = fbits(ap[0]);
                af[mi][1] = fbits(ap[8*GPAD]);
                af[mi][2] = fbits(ap[4]);
                af[mi][3] = fbits(ap[8*GPAD + 4]);
            }
            #pragma unroll
            for (int nj = 0; nj < 4; nj++) {
                const float* bp = bs + (wn + nj*8 + r4)*GPAD + kk + c4;
                uint32_t b0 = fbits(bp[0]), b1 = fbits(bp[4]);
                #pragma unroll
                for (int mi = 0; mi < 4; mi++)
                    mma_tf32(acc[mi][nj], af[mi][0], af[mi][1], af[mi][2], af[mi][3], b0, b1);
            }
        }
        __syncthreads();
    }

    #pragma unroll
    for (int mi = 0; mi < 4; mi++) {
        #pragma unroll
        for (int r2 = 0; r2 < 2; r2++) {
            int m = by*128 + wm + mi*16 + r4 + r2*8;
            int orow = permOut ? ((m & 1023)*B_ + (m >> 10)) : m;
            float* yp = Y + (size_t)orow*1024 + bx*128 + wn;
            const float* bi = bias + bx*128 + wn;
            #pragma unroll
            for (int nj = 0; nj < 4; nj++) {
                int c = nj*8 + 2*c4;
                float2 val;
                val.x = acc[mi][nj][r2*2 + 0] + bi[c];
                val.y = acc[mi][nj][r2*2 + 1] + bi[c + 1];
                if (roundOut) { val.x = tfround(val.x); val.y = tfround(val.y); }
                *(float2*)(yp + c) = val;
            }
        }
    }
}

__global__ void __launch_bounds__(256) tgemm_qkv(
    const float* __restrict__ bq, const float* __restrict__ bk,
    const float* __restrict__ bv, float* __restrict__ Y)
{
    __shared__ float As[2][GSTG];
    __shared__ float Bs[2][GSTG];
    int sel = blockIdx.z;
    const float* bi = (sel == 0) ? bq : (sel == 1) ? bk : bv;
    tgemm_body(g_xtf, g_wtf + (size_t)sel*E_*E_, bi, Y + (size_t)sel*B_*S_*E_,
               1, 0, sel == 2, blockIdx.x, blockIdx.y, As, Bs);
}

__global__ void __launch_bounds__(256) tgemm_wo(
    const float* __restrict__ bias, float* __restrict__ Y)
{
    __shared__ float As[2][GSTG];
    __shared__ float Bs[2][GSTG];
    tgemm_body(g_ctx, g_wtf + (size_t)3*E_*E_, bias, Y,
               0, 1, 0, blockIdx.x, blockIdx.y, As, Bs);
}

// ---------------------------------------------------------------------------
__global__ void gproj_kernel(const float* __restrict__ Wgq, const float* __restrict__ bgq,
                             const float* __restrict__ Wgk, const float* __restrict__ bgk)
{
    const float* Wg = blockIdx.y ? Wgk : Wgq;
    const float* bg = blockIdx.y ? bgk : bgq;
    float* out      = blockIdx.y ? g_gk : g_gq;
    int gw = (blockIdx.x * blockDim.x + threadIdx.x) >> 5;
    int lane = threadIdx.x & 31;
    int b = gw >> 10, o = gw & 1023;
    float acc = 0.f;
    #pragma unroll
    for (int e = lane * 4; e < E_; e += 128) {
        float4 gv = *(const float4*)&g_g[b*E_ + e];
        float4 wv = *(const float4*)&Wg[(size_t)o*E_ + e];
        acc += gv.x*wv.x + gv.y*wv.y + gv.z*wv.z + gv.w*wv.w;
    }
    #pragma unroll
    for (int of = 16; of; of >>= 1) acc += __shfl_xor_sync(0xffffffffu, acc, of);
    if (lane == 0) out[b*E_ + o] = acc + bg[o];
}

__global__ void gate_kernel(float* __restrict__ qkv,
                            const float* __restrict__ wvq, const float* __restrict__ bvq,
                            const float* __restrict__ wgq, const float* __restrict__ bgq,
                            const float* __restrict__ wvk, const float* __restrict__ bvk,
                            const float* __restrict__ wgk, const float* __restrict__ bgk)
{
    int z = blockIdx.y;
    float* buf        = qkv + (size_t)z * B_*S_*E_;
    const float* gbuf = z ? g_gk : g_gq;
    const float* wv   = z ? wvk : wvq;
    const float* bvp  = z ? bvk : bvq;
    const float* wg   = z ? wgk : wgq;
    const float* bgp  = z ? bgk : bgq;

    int gw   = (blockIdx.x * blockDim.x + threadIdx.x) >> 5;
    int lane = threadIdx.x & 31;
    int b = gw >> 14, h = (gw >> 10) & 15, s = gw & 1023;
    size_t off = ((size_t)(b*S_ + s))*E_ + h*D_;
    int goff = b*E_ + h*D_;
    float q0 = buf[off + lane],        q1 = buf[off + 32 + lane];
    float g0 = gbuf[goff + lane],      g1 = gbuf[goff + 32 + lane];
    float part = q0*wv[lane] + q1*wv[32 + lane] + g0*wg[lane] + g1*wg[32 + lane];
    #pragma unroll
    for (int o = 16; o; o >>= 1) part += __shfl_xor_sync(0xffffffffu, part, o);
    float alpha = 1.f / (1.f + __expf(-(part + bvp[0] + bgp[0])));
    buf[off + lane]      = tfround(q0 + alpha * (g0 - q0));
    buf[off + 32 + lane] = tfround(q1 + alpha * (g1 - q1));
}

// ---------------------------------------------------------------------------
// fused attention: 32 q-rows/CTA, 512 threads (16 warps), 128-key cp.async
// double-buffered chunks. K stride 68, V stride 72 (both conflict-free).
// All MMA operands pre-rounded tf32 -> raw-bit loads only.
#define SCP 1028
#define KW 68
#define VW 72
#define CH 128
#define ATTN_SMEM_FLOATS (32*SCP + 32*KW + 2*CH*VW + 1024)
#define ATTN_SMEM_BYTES (ATTN_SMEM_FLOATS * 4)

__global__ void __launch_bounds__(512) attn_kernel(
    const float* __restrict__ q, const float* __restrict__ k,
    const float* __restrict__ v, const int* __restrict__ mask,
    float* __restrict__ p_out, float* __restrict__ ctx)
{
    extern __shared__ float sm[];
    float* sc  = sm;                    // [32][1028]
    float* qs  = sc + 32*SCP;           // [32][68]
    float* kvs = qs + 32*KW;            // [2][128][72] (K inner stride 68)
    float* mk  = kvs + 2*CH*VW;         // [1024]

    const int b = blockIdx.z, h = blockIdx.y, i0 = blockIdx.x * 32;
    const int tid = threadIdx.x;
    const int lane = tid & 31, warp = tid >> 5;
    const int r4 = lane >> 2, c4 = lane & 3;
    const int mi_w = warp & 1;           // m16 tile (rows mi_w*16..)
    const int njg  = warp >> 1;          // 0..7: phase1 16-col group / phase3 n8 tile

    uint32_t kvBase = (uint32_t)__cvta_generic_to_shared(kvs);

    // chunk c: 0..7 = K (stride 68), 8..15 = V (stride 72); 128 keys each
    auto issue_chunk = [&](int c) {
        const float* src = (c < 8) ? k : v;
        int stride = (c < 8) ? KW : VW;
        int j0 = (c & 7) * CH;
        uint32_t so = (uint32_t)((c & 1) * CH * VW * 4);
        #pragma unroll
        for (int t = 0; t < 4; t++) {
            int idx = tid + t*512;
            int j = idx >> 4, d4 = (idx & 15) * 4;
            cp16(kvBase + so + (j*stride + d4)*4,
                 src + ((size_t)(b*S_ + j0 + j))*E_ + h*D_ + d4);
        }
        asm volatile("cp.async.commit_group;" ::: "memory");
    };

    issue_chunk(0);

    {
        int i = tid >> 4, d4 = (tid & 15) * 4;
        float4 qv = *(const float4*)&q[((size_t)(b*S_ + i0 + i))*E_ + h*D_ + d4];
        qv.x *= 0.125f; qv.y *= 0.125f; qv.z *= 0.125f; qv.w *= 0.125f;
        *(float4*)&qs[i*KW + d4] = qv;
    }
    for (int j = tid; j < S_; j += 512) mk[j] = (float)mask[b*S_ + j];
    __syncthreads();

    // preload q A-fragments (32 regs) for this warp's m16 tile
    uint32_t qa[8][4];
    #pragma unroll
    for (int kk8 = 0; kk8 < 8; kk8++) {
        const float* ap = qs + (mi_w*16 + r4)*KW + kk8*8 + c4;
        qa[kk8][0] = fbits(ap[0]);
        qa[kk8][1] = fbits(ap[8*KW]);
        qa[kk8][2] = fbits(ap[4]);
        qa[kk8][3] = fbits(ap[8*KW + 4]);
    }

    // ---- phase 1: scores = q @ k^T, 8 chunks of 128 keys ----
    for (int jt = 0; jt < 8; jt++) {
        issue_chunk(jt + 1);   // jt==7 prefetches V chunk 0
        asm volatile("cp.async.wait_group 1;" ::: "memory");
        __syncthreads();
        const float* kc = kvs + (jt & 1) * CH * VW;

        float acc[2][4] = {{0,0,0,0},{0,0,0,0}};
        #pragma unroll
        for (int kk8 = 0; kk8 < 8; kk8++) {
            #pragma unroll
            for (int u = 0; u < 2; u++) {
                const float* bp = kc + (njg*16 + u*8 + r4)*KW + kk8*8 + c4;
                mma_tf32(acc[u], qa[kk8][0], qa[kk8][1], qa[kk8][2], qa[kk8][3],
                         fbits(bp[0]), fbits(bp[4]));
            }
        }
        int r = mi_w*16 + r4;
        #pragma unroll
        for (int u = 0; u < 2; u++) {
            int n0 = jt*CH + njg*16 + u*8 + 2*c4;
            *(float2*)&sc[r*SCP + n0]     = make_float2(acc[u][0], acc[u][1]);
            *(float2*)&sc[(r+8)*SCP + n0] = make_float2(acc[u][2], acc[u][3]);
        }
        __syncthreads();
    }

    // ---- phase 2: softmax + streaming p write (V chunk 0 in flight) ----
    for (int r = warp; r < 32; r += 16) {
        float* row = sc + r * SCP;
        float mx = -1e30f;
        for (int j = lane; j < 1024; j += 32) {
            float sv = (mk[j] != 0.f) ? row[j] : -1e9f;
            row[j] = sv;
            mx = fmaxf(mx, sv);
        }
        #pragma unroll
        for (int o = 16; o; o >>= 1) mx = fmaxf(mx, __shfl_xor_sync(0xffffffffu, mx, o));
        float sum = 0.f;
        for (int j = lane; j < 1024; j += 32) {
            float e = __expf(row[j] - mx);
            row[j] = e;
            sum += e;
        }
        #pragma unroll
        for (int o = 16; o; o >>= 1) sum += __shfl_xor_sync(0xffffffffu, sum, o);
        float inv = 1.f / sum;
        float* prow = p_out + (((size_t)(b*H_ + h))*S_ + i0 + r) * S_;
        for (int j = lane; j < 1024; j += 32) {
            float pv = row[j] * inv;
            __stcs(prow + j, pv);      // streaming: don't evict V from L2
            row[j] = tfround(pv);      // tf32 for phase-3 A operand
        }
    }

    // ---- phase 3: out = p @ v, 8 chunks of 128 keys, warp = (m16, n8) ----
    float oacc[4] = {0,0,0,0};
    for (int c = 8; c < 16; c++) {
        if (c < 15) {
            issue_chunk(c + 1);
            asm volatile("cp.async.wait_group 1;" ::: "memory");
        } else {
            asm volatile("cp.async.wait_group 0;" ::: "memory");
        }
        __syncthreads();
        const float* vc = kvs + (c & 1) * CH * VW;
        int j0 = (c - 8) * CH;
        #pragma unroll
        for (int kk = 0; kk < CH; kk += 8) {
            const float* ap = sc + (mi_w*16 + r4)*SCP + j0 + kk + c4;
            uint32_t a0 = fbits(ap[0]), a1 = fbits(ap[8*SCP]);
            uint32_t a2 = fbits(ap[4]), a3 = fbits(ap[8*SCP + 4]);
            const float* bp = vc + (kk + c4)*VW + njg*8 + r4;
            mma_tf32(oacc, a0, a1, a2, a3, fbits(bp[0]), fbits(bp[4*VW]));
        }
        __syncthreads();
    }
    {
        int r = mi_w*16 + r4;
        int cc = njg*8 + 2*c4;
        size_t o0 = ((size_t)(b*S_ + i0 + r))*E_ + h*D_ + cc;
        size_t o1 = ((size_t)(b*S_ + i0 + r + 8))*E_ + h*D_ + cc;
        *(float2*)&ctx[o0] = make_float2(tfround(oacc[0]), tfround(oacc[1]));
        *(float2*)&ctx[o1] = make_float2(tfround(oacc[2]), tfround(oacc[3]));
    }
}

// ---------------------------------------------------------------------------
extern "C" void kernel_launch(void* const* d_in, const int* in_sizes, int n_in,
                              void* d_out, int out_size)
{
    const float* x    = (const float*)d_in[0];
    const int*   mask = (const int*)  d_in[1];
    const float* Wq = (const float*)d_in[2];
    const float* bq = (const float*)d_in[3];
    const float* Wk = (const float*)d_in[4];
    const float* bk = (const float*)d_in[5];
    const float* Wv = (const float*)d_in[6];
    const float* bv = (const float*)d_in[7];
    const float* Wo = (const float*)d_in[8];
    const float* bo = (const float*)d_in[9];
    const float* Wgq = (const float*)d_in[10];
    const float* bgq = (const float*)d_in[11];
    const float* Wgk = (const float*)d_in[12];
    const float* bgk = (const float*)d_in[13];
    const float* qg_wq = (const float*)d_in[14];
    const float* qg_bq = (const float*)d_in[15];
    const float* qg_wk = (const float*)d_in[16];
    const float* qg_bk = (const float*)d_in[17];
    const float* kg_wq = (const float*)d_in[18];
    const float* kg_bq = (const float*)d_in[19];
    const float* kg_wk = (const float*)d_in[20];
    const float* kg_bk = (const float*)d_in[21];

    float* out   = (float*)d_out;
    float* p_out = out + (size_t)S_ * B_ * E_;

    float *qkvb, *ctxb;
    cudaGetSymbolAddress((void**)&qkvb, g_qkv);
    cudaGetSymbolAddress((void**)&ctxb, g_ctx);
    float* qb = qkvb;
    float* kb = qkvb + (size_t)B_*S_*E_;
    float* vb = qkvb + 2*(size_t)B_*S_*E_;

    cudaFuncSetAttribute(attn_kernel, cudaFuncAttributeMaxDynamicSharedMemorySize,
                         ATTN_SMEM_BYTES);

    round_all<<<8192, 256>>>((const float4*)x, (const float4*)Wq,
                             (const float4*)Wk, (const float4*)Wv, (const float4*)Wo);
    msum_kernel<<<1, 128>>>(mask);
    mean_kernel<<<dim3(E_/64, B_), 256>>>(x, mask);

    tgemm_qkv<<<dim3(8, 32, 3), 256>>>(bq, bk, bv, qkvb);

    gproj_kernel<<<dim3(512, 2), 256>>>(Wgq, bgq, Wgk, bgk);

    gate_kernel<<<dim3(8192, 2), 256>>>(qkvb,
        qg_wq, qg_bq, qg_wk, qg_bk,
        kg_wq, kg_bq, kg_wk, kg_bk);

    attn_kernel<<<dim3(S_/32, H_, B_), 512, ATTN_SMEM_BYTES>>>(
        qb, kb, vb, mask, p_out, ctxb);

    tgemm_wo<<<dim3(8, 32), 256>>>(bo, out);
}